// round 8
// baseline (speedup 1.0000x reference)
#include <cuda_runtime.h>
#include <math.h>

#define MAXN 100000
#define MAXE 3200000

// Scratch (device globals — allocation-free per harness rules)
__device__ int   g_cnt[MAXN];
__device__ int   g_ptr[MAXN + 1];
__device__ int   g_cur[MAXN];
__device__ int   g_src[MAXE];
__device__ float g_dis[MAXN];
__device__ float g_h1s[(size_t)MAXN * 64];   // h1 * dis[row]
__device__ float g_agg1[(size_t)MAXN * 64];  // Σ_in h1s + self (unscaled by dis[col])
__device__ float g_h2s[(size_t)MAXN * 32];   // h2 * dis[row]

__device__ __forceinline__ float elu_f(float v) { return v > 0.f ? v : expm1f(v); }

// ---------------- CSR build ----------------
__global__ void k_zero_cnt(int N) {
    int i = blockIdx.x * blockDim.x + threadIdx.x;
    if (i < N) g_cnt[i] = 0;
}

__global__ void k_count(const int* __restrict__ col, int E) {
    int e = blockIdx.x * blockDim.x + threadIdx.x;
    if (e < E) atomicAdd(&g_cnt[col[e]], 1);
}

// Single-block exclusive scan of g_cnt -> g_ptr / g_cur; also dis = rsqrt(cnt+1).
__global__ void __launch_bounds__(1024) k_scan(int N) {
    __shared__ int sh[1024];
    const int t = threadIdx.x;
    const int C = (N + 1023) / 1024;
    const int base = t * C;

    int s = 0;
    for (int i = 0; i < C; i++) {
        int idx = base + i;
        if (idx < N) s += g_cnt[idx];
    }
    sh[t] = s;
    __syncthreads();
    for (int off = 1; off < 1024; off <<= 1) {
        int v = 0;
        if (t >= off) v = sh[t - off];
        __syncthreads();
        if (t >= off) sh[t] += v;
        __syncthreads();
    }
    int run = sh[t] - s;   // exclusive prefix
    for (int i = 0; i < C; i++) {
        int idx = base + i;
        if (idx < N) {
            int c = g_cnt[idx];
            g_ptr[idx] = run;
            g_cur[idx] = run;
            g_dis[idx] = rsqrtf((float)c + 1.0f);   // +1 = self loop
            run += c;
        }
    }
    if (t == 1023) g_ptr[N] = run;
}

__global__ void k_fill(const int* __restrict__ rowi, const int* __restrict__ coli, int E) {
    int e = blockIdx.x * blockDim.x + threadIdx.x;
    if (e >= E) return;
    int c = coli[e];
    int pos = atomicAdd(&g_cur[c], 1);
    g_src[pos] = rowi[e];
}

// ---------------- GEMM 1: h1s = (x @ W1) * dis[row]  (256 -> 64) ----------------
__global__ void __launch_bounds__(256) k_gemm1(const float* __restrict__ x,
                                               const float* __restrict__ W1, int N) {
    __shared__ float xT[32][260];
    __shared__ float Wt[32][64];

    const int tid = threadIdx.x;
    const int m0 = blockIdx.x * 256;
    const int r0 = (tid >> 3) * 8;
    const int c0 = (tid & 7) * 8;

    float acc[8][8];
#pragma unroll
    for (int i = 0; i < 8; i++)
#pragma unroll
        for (int j = 0; j < 8; j++) acc[i][j] = 0.f;

    const int myrow = m0 + tid;
    for (int kt = 0; kt < 8; kt++) {
        const int k0 = kt * 32;
        {
            float4 v[8];
            if (myrow < N) {
                const float4* src = (const float4*)(x + (size_t)myrow * 256 + k0);
#pragma unroll
                for (int q = 0; q < 8; q++) v[q] = src[q];
            } else {
#pragma unroll
                for (int q = 0; q < 8; q++) v[q] = make_float4(0.f, 0.f, 0.f, 0.f);
            }
#pragma unroll
            for (int q = 0; q < 8; q++) {
                xT[4 * q + 0][tid] = v[q].x;
                xT[4 * q + 1][tid] = v[q].y;
                xT[4 * q + 2][tid] = v[q].z;
                xT[4 * q + 3][tid] = v[q].w;
            }
        }
        {
            const float4* src = (const float4*)(W1 + (size_t)k0 * 64);
            float4* dst = (float4*)Wt;
            dst[tid] = src[tid];
            dst[tid + 256] = src[tid + 256];
        }
        __syncthreads();

#pragma unroll
        for (int kk = 0; kk < 32; kk++) {
            float4 xa = *(const float4*)&xT[kk][r0];
            float4 xb = *(const float4*)&xT[kk][r0 + 4];
            float4 wa = *(const float4*)&Wt[kk][c0];
            float4 wb = *(const float4*)&Wt[kk][c0 + 4];
            float xs[8] = {xa.x, xa.y, xa.z, xa.w, xb.x, xb.y, xb.z, xb.w};
            float ws[8] = {wa.x, wa.y, wa.z, wa.w, wb.x, wb.y, wb.z, wb.w};
#pragma unroll
            for (int i = 0; i < 8; i++)
#pragma unroll
                for (int j = 0; j < 8; j++) acc[i][j] += xs[i] * ws[j];
        }
        __syncthreads();
    }

#pragma unroll
    for (int i = 0; i < 8; i++) {
        int m = m0 + r0 + i;
        if (m >= N) break;
        float d = g_dis[m];
        float4 a = make_float4(acc[i][0] * d, acc[i][1] * d, acc[i][2] * d, acc[i][3] * d);
        float4 b = make_float4(acc[i][4] * d, acc[i][5] * d, acc[i][6] * d, acc[i][7] * d);
        float4* o1 = (float4*)(g_h1s + (size_t)m * 64 + c0);
        o1[0] = a; o1[1] = b;
    }
}

// ---------------- aggregation 1 (CSR gather): agg1[c] = h1s[c] + Σ_src h1s[r] ----------------
// 16 threads per node (float4 lanes over 64 ch).
__global__ void k_agg1(int N) {
    int t = blockIdx.x * blockDim.x + threadIdx.x;
    int node = t >> 4, l = t & 15;
    if (node >= N) return;
    int s = g_ptr[node], e = g_ptr[node + 1];
    const float4* H = (const float4*)g_h1s;
    float4 acc = H[(size_t)node * 16 + l];   // self loop
    int i = s;
    for (; i + 4 <= e; i += 4) {
        int r0 = g_src[i], r1 = g_src[i + 1], r2 = g_src[i + 2], r3 = g_src[i + 3];
        float4 a = H[(size_t)r0 * 16 + l];
        float4 b = H[(size_t)r1 * 16 + l];
        float4 c = H[(size_t)r2 * 16 + l];
        float4 d = H[(size_t)r3 * 16 + l];
        acc.x += (a.x + b.x) + (c.x + d.x);
        acc.y += (a.y + b.y) + (c.y + d.y);
        acc.z += (a.z + b.z) + (c.z + d.z);
        acc.w += (a.w + b.w) + (c.w + d.w);
    }
    for (; i < e; i++) {
        int r = g_src[i];
        float4 a = H[(size_t)r * 16 + l];
        acc.x += a.x; acc.y += a.y; acc.z += a.z; acc.w += a.w;
    }
    ((float4*)g_agg1)[(size_t)node * 16 + l] = acc;
}

// ---------------- GEMM 2: h2s = (elu(dis*agg1 + b1) @ W2) * dis  (64 -> 32) ----------------
__global__ void __launch_bounds__(128) k_gemm2(const float* __restrict__ W2,
                                               const float* __restrict__ b1, int N) {
    __shared__ float aT[32][260];
    __shared__ float Wt[64][32];
    __shared__ float bs[64];

    const int tid = threadIdx.x;
    const int m0 = blockIdx.x * 256;
    const int r0 = (tid >> 2) * 8;
    const int c0 = (tid & 3) * 8;

    {
        const float4* src = (const float4*)W2;
        float4* dst = (float4*)Wt;
#pragma unroll
        for (int q = 0; q < 4; q++) dst[tid + 128 * q] = src[tid + 128 * q];
        if (tid < 64) bs[tid] = b1[tid];
    }
    __syncthreads();

    float acc[8][8];
#pragma unroll
    for (int i = 0; i < 8; i++)
#pragma unroll
        for (int j = 0; j < 8; j++) acc[i][j] = 0.f;

    for (int kt = 0; kt < 2; kt++) {
        const int k0 = kt * 32;
        __syncthreads();
#pragma unroll
        for (int half = 0; half < 2; half++) {
            int lm = tid + 128 * half;
            int m = m0 + lm;
            if (m < N) {
                float d = g_dis[m];
                const float4* src = (const float4*)(g_agg1 + (size_t)m * 64 + k0);
#pragma unroll
                for (int q = 0; q < 8; q++) {
                    float4 v = src[q];
                    aT[4 * q + 0][lm] = elu_f(d * v.x + bs[k0 + 4 * q + 0]);
                    aT[4 * q + 1][lm] = elu_f(d * v.y + bs[k0 + 4 * q + 1]);
                    aT[4 * q + 2][lm] = elu_f(d * v.z + bs[k0 + 4 * q + 2]);
                    aT[4 * q + 3][lm] = elu_f(d * v.w + bs[k0 + 4 * q + 3]);
                }
            } else {
#pragma unroll
                for (int q = 0; q < 32; q++) aT[q][lm] = 0.f;
            }
        }
        __syncthreads();

#pragma unroll
        for (int kk = 0; kk < 32; kk++) {
            float4 xa = *(const float4*)&aT[kk][r0];
            float4 xb = *(const float4*)&aT[kk][r0 + 4];
            float4 wa = *(const float4*)&Wt[k0 + kk][c0];
            float4 wb = *(const float4*)&Wt[k0 + kk][c0 + 4];
            float xs[8] = {xa.x, xa.y, xa.z, xa.w, xb.x, xb.y, xb.z, xb.w};
            float ws[8] = {wa.x, wa.y, wa.z, wa.w, wb.x, wb.y, wb.z, wb.w};
#pragma unroll
            for (int i = 0; i < 8; i++)
#pragma unroll
                for (int j = 0; j < 8; j++) acc[i][j] += xs[i] * ws[j];
        }
    }

#pragma unroll
    for (int i = 0; i < 8; i++) {
        int m = m0 + r0 + i;
        if (m >= N) break;
        float d = g_dis[m];
        float4 a = make_float4(acc[i][0] * d, acc[i][1] * d, acc[i][2] * d, acc[i][3] * d);
        float4 b = make_float4(acc[i][4] * d, acc[i][5] * d, acc[i][6] * d, acc[i][7] * d);
        float4* o1 = (float4*)(g_h2s + (size_t)m * 32 + c0);
        o1[0] = a; o1[1] = b;
    }
}

// ---------------- aggregation 2 + final head fused ----------------
// 8 threads per node; agg in regs, ELU+b2, dot with Wc, shfl-reduce, store scalar.
__global__ void k_agg2_final(const float* __restrict__ Wc, const float* __restrict__ b2,
                             const float* __restrict__ bc, float* __restrict__ out, int N) {
    __shared__ float wcs[32], b2s[32];
    if (threadIdx.x < 32) {
        wcs[threadIdx.x] = Wc[threadIdx.x];
        b2s[threadIdx.x] = b2[threadIdx.x];
    }
    __syncthreads();
    int t = blockIdx.x * blockDim.x + threadIdx.x;
    int node = t >> 3, l = t & 7;
    bool valid = (node < N);
    int nd = valid ? node : N - 1;   // keep all lanes resident for shfl

    int s = g_ptr[nd], e = g_ptr[nd + 1];
    const float4* H = (const float4*)g_h2s;
    float4 acc = H[(size_t)nd * 8 + l];   // self loop
    int i = s;
    for (; i + 4 <= e; i += 4) {
        int r0 = g_src[i], r1 = g_src[i + 1], r2 = g_src[i + 2], r3 = g_src[i + 3];
        float4 a = H[(size_t)r0 * 8 + l];
        float4 b = H[(size_t)r1 * 8 + l];
        float4 c = H[(size_t)r2 * 8 + l];
        float4 d = H[(size_t)r3 * 8 + l];
        acc.x += (a.x + b.x) + (c.x + d.x);
        acc.y += (a.y + b.y) + (c.y + d.y);
        acc.z += (a.z + b.z) + (c.z + d.z);
        acc.w += (a.w + b.w) + (c.w + d.w);
    }
    for (; i < e; i++) {
        int r = g_src[i];
        float4 a = H[(size_t)r * 8 + l];
        acc.x += a.x; acc.y += a.y; acc.z += a.z; acc.w += a.w;
    }

    float d = g_dis[nd];
    int j0 = l * 4;
    float part = elu_f(d * acc.x + b2s[j0 + 0]) * wcs[j0 + 0]
               + elu_f(d * acc.y + b2s[j0 + 1]) * wcs[j0 + 1]
               + elu_f(d * acc.z + b2s[j0 + 2]) * wcs[j0 + 2]
               + elu_f(d * acc.w + b2s[j0 + 3]) * wcs[j0 + 3];
    part += __shfl_xor_sync(0xFFFFFFFFu, part, 4);
    part += __shfl_xor_sync(0xFFFFFFFFu, part, 2);
    part += __shfl_xor_sync(0xFFFFFFFFu, part, 1);
    if (valid && l == 0) out[node] = part + __ldg(bc);
}

extern "C" void kernel_launch(void* const* d_in, const int* in_sizes, int n_in,
                              void* d_out, int out_size) {
    const float* x = (const float*)d_in[0];
    const int* ei = (const int*)d_in[1];   // int32
    const float* W1 = (const float*)d_in[2];
    const float* b1 = (const float*)d_in[3];
    const float* W2 = (const float*)d_in[4];
    const float* b2 = (const float*)d_in[5];
    const float* Wc = (const float*)d_in[6];
    const float* bc = (const float*)d_in[7];
    float* out = (float*)d_out;

    int N = in_sizes[0] / 256;
    int E = in_sizes[1] / 2;
    const int* erow = ei;       // source (gather)
    const int* ecol = ei + E;   // target (aggregation)

    const int T = 256;
    // CSR build (shared by both layers) + dis
    k_zero_cnt<<<(N + T - 1) / T, T>>>(N);
    k_count<<<(E + T - 1) / T, T>>>(ecol, E);
    k_scan<<<1, 1024>>>(N);
    k_fill<<<(E + T - 1) / T, T>>>(erow, ecol, E);
    // layer 1
    k_gemm1<<<(N + 255) / 256, 256>>>(x, W1, N);
    {
        long long th = (long long)N * 16;
        k_agg1<<<(int)((th + T - 1) / T), T>>>(N);
    }
    // layer 2
    k_gemm2<<<(N + 255) / 256, 128>>>(W2, b1, N);
    // aggregation 2 + head fused
    {
        long long th = (long long)N * 8;
        k_agg2_final<<<(int)((th + T - 1) / T), T>>>(Wc, b2, bc, out, N);
    }
}

// round 9
// speedup vs baseline: 1.0432x; 1.0432x over previous
#include <cuda_runtime.h>
#include <math.h>

#define MAXN 100000
#define MAXE 3200000

__device__ int   g_cnt[MAXN];
__device__ int   g_ptr[MAXN + 1];
__device__ int   g_cur[MAXN];
__device__ int   g_src[MAXE];
__device__ float g_dis[MAXN];
__device__ float g_h1s[(size_t)MAXN * 64];   // h1 * dis[row]
__device__ float g_agg1[(size_t)MAXN * 64];  // Σ_in h1s + self (unscaled by dis[col])
__device__ float g_h2s[(size_t)MAXN * 32];   // h2 * dis[row]

__device__ __forceinline__ float elu_f(float v) { return v > 0.f ? v : expm1f(v); }

// ---------------- CSR build ----------------
__global__ void k_zero_cnt(int N) {
    int i = blockIdx.x * blockDim.x + threadIdx.x;
    if (i < N) g_cnt[i] = 0;
}

// 4 edges/thread, REDs pipeline freely (no return value)
__global__ void k_count(const int* __restrict__ col, int E) {
    int base = (blockIdx.x * blockDim.x + threadIdx.x) * 4;
    if (base >= E) return;
    int n = min(4, E - base);
    int c[4];
#pragma unroll
    for (int q = 0; q < 4; q++) if (q < n) c[q] = col[base + q];
#pragma unroll
    for (int q = 0; q < 4; q++) if (q < n) atomicAdd(&g_cnt[c[q]], 1);
}

// Single-block exclusive scan of g_cnt -> g_ptr / g_cur; also dis = rsqrt(cnt+1).
__global__ void __launch_bounds__(1024) k_scan(int N) {
    __shared__ int sh[1024];
    const int t = threadIdx.x;
    const int C = (N + 1023) / 1024;
    const int base = t * C;

    int s = 0;
    for (int i = 0; i < C; i++) {
        int idx = base + i;
        if (idx < N) s += g_cnt[idx];
    }
    sh[t] = s;
    __syncthreads();
    for (int off = 1; off < 1024; off <<= 1) {
        int v = 0;
        if (t >= off) v = sh[t - off];
        __syncthreads();
        if (t >= off) sh[t] += v;
        __syncthreads();
    }
    int run = sh[t] - s;   // exclusive prefix
    for (int i = 0; i < C; i++) {
        int idx = base + i;
        if (idx < N) {
            int c = g_cnt[idx];
            g_ptr[idx] = run;
            g_cur[idx] = run;
            g_dis[idx] = rsqrtf((float)c + 1.0f);   // +1 = self loop
            run += c;
        }
    }
    if (t == 1023) g_ptr[N] = run;
}

// 4 edges/thread: batch the ATOMG-with-return latencies (~318cyc each overlap)
__global__ void k_fill(const int* __restrict__ rowi, const int* __restrict__ coli, int E) {
    int base = (blockIdx.x * blockDim.x + threadIdx.x) * 4;
    if (base >= E) return;
    int n = min(4, E - base);
    int c[4], r[4], pos[4];
#pragma unroll
    for (int q = 0; q < 4; q++) if (q < n) { c[q] = coli[base + q]; r[q] = rowi[base + q]; }
#pragma unroll
    for (int q = 0; q < 4; q++) if (q < n) pos[q] = atomicAdd(&g_cur[c[q]], 1);
#pragma unroll
    for (int q = 0; q < 4; q++) if (q < n) g_src[pos[q]] = r[q];
}

// ---------------- GEMM 1: h1s = (x @ W1) * dis[row]  (256 -> 64) ----------------
__global__ void __launch_bounds__(256) k_gemm1(const float* __restrict__ x,
                                               const float* __restrict__ W1, int N) {
    __shared__ float xT[32][260];
    __shared__ float Wt[32][64];

    const int tid = threadIdx.x;
    const int m0 = blockIdx.x * 256;
    const int r0 = (tid >> 3) * 8;
    const int c0 = (tid & 7) * 8;

    float acc[8][8];
#pragma unroll
    for (int i = 0; i < 8; i++)
#pragma unroll
        for (int j = 0; j < 8; j++) acc[i][j] = 0.f;

    const int myrow = m0 + tid;
    for (int kt = 0; kt < 8; kt++) {
        const int k0 = kt * 32;
        {
            float4 v[8];
            if (myrow < N) {
                const float4* src = (const float4*)(x + (size_t)myrow * 256 + k0);
#pragma unroll
                for (int q = 0; q < 8; q++) v[q] = src[q];
            } else {
#pragma unroll
                for (int q = 0; q < 8; q++) v[q] = make_float4(0.f, 0.f, 0.f, 0.f);
            }
#pragma unroll
            for (int q = 0; q < 8; q++) {
                xT[4 * q + 0][tid] = v[q].x;
                xT[4 * q + 1][tid] = v[q].y;
                xT[4 * q + 2][tid] = v[q].z;
                xT[4 * q + 3][tid] = v[q].w;
            }
        }
        {
            const float4* src = (const float4*)(W1 + (size_t)k0 * 64);
            float4* dst = (float4*)Wt;
            dst[tid] = src[tid];
            dst[tid + 256] = src[tid + 256];
        }
        __syncthreads();

#pragma unroll
        for (int kk = 0; kk < 32; kk++) {
            float4 xa = *(const float4*)&xT[kk][r0];
            float4 xb = *(const float4*)&xT[kk][r0 + 4];
            float4 wa = *(const float4*)&Wt[kk][c0];
            float4 wb = *(const float4*)&Wt[kk][c0 + 4];
            float xs[8] = {xa.x, xa.y, xa.z, xa.w, xb.x, xb.y, xb.z, xb.w};
            float ws[8] = {wa.x, wa.y, wa.z, wa.w, wb.x, wb.y, wb.z, wb.w};
#pragma unroll
            for (int i = 0; i < 8; i++)
#pragma unroll
                for (int j = 0; j < 8; j++) acc[i][j] += xs[i] * ws[j];
        }
        __syncthreads();
    }

#pragma unroll
    for (int i = 0; i < 8; i++) {
        int m = m0 + r0 + i;
        if (m >= N) break;
        float d = g_dis[m];
        float4 a = make_float4(acc[i][0] * d, acc[i][1] * d, acc[i][2] * d, acc[i][3] * d);
        float4 b = make_float4(acc[i][4] * d, acc[i][5] * d, acc[i][6] * d, acc[i][7] * d);
        float4* o1 = (float4*)(g_h1s + (size_t)m * 64 + c0);
        o1[0] = a; o1[1] = b;
    }
}

// ---------------- aggregation 1 (CSR gather, pipelined unroll-8) ----------------
// 16 threads per node (float4 lanes over 64 ch). Two accumulators, 8 loads in flight.
__global__ void k_agg1(int N) {
    int t = blockIdx.x * blockDim.x + threadIdx.x;
    int node = t >> 4, l = t & 15;
    if (node >= N) return;
    int s = g_ptr[node], e = g_ptr[node + 1];
    const float4* H = (const float4*)g_h1s;
    float4 accA = H[(size_t)node * 16 + l];   // self loop
    float4 accB = make_float4(0.f, 0.f, 0.f, 0.f);
    int i = s;
    for (; i + 8 <= e; i += 8) {
        int r[8];
#pragma unroll
        for (int q = 0; q < 8; q++) r[q] = g_src[i + q];
        float4 v[8];
#pragma unroll
        for (int q = 0; q < 8; q++) v[q] = H[(size_t)r[q] * 16 + l];
#pragma unroll
        for (int q = 0; q < 4; q++) {
            accA.x += v[q].x; accA.y += v[q].y; accA.z += v[q].z; accA.w += v[q].w;
        }
#pragma unroll
        for (int q = 4; q < 8; q++) {
            accB.x += v[q].x; accB.y += v[q].y; accB.z += v[q].z; accB.w += v[q].w;
        }
    }
    for (; i < e; i++) {
        int r = g_src[i];
        float4 a = H[(size_t)r * 16 + l];
        accA.x += a.x; accA.y += a.y; accA.z += a.z; accA.w += a.w;
    }
    accA.x += accB.x; accA.y += accB.y; accA.z += accB.z; accA.w += accB.w;
    ((float4*)g_agg1)[(size_t)node * 16 + l] = accA;
}

// ---------------- GEMM 2: h2s = (elu(dis*agg1 + b1) @ W2) * dis  (64 -> 32) ----------------
__global__ void __launch_bounds__(128) k_gemm2(const float* __restrict__ W2,
                                               const float* __restrict__ b1, int N) {
    __shared__ float aT[32][260];
    __shared__ float Wt[64][32];
    __shared__ float bs[64];

    const int tid = threadIdx.x;
    const int m0 = blockIdx.x * 256;
    const int r0 = (tid >> 2) * 8;
    const int c0 = (tid & 3) * 8;

    {
        const float4* src = (const float4*)W2;
        float4* dst = (float4*)Wt;
#pragma unroll
        for (int q = 0; q < 4; q++) dst[tid + 128 * q] = src[tid + 128 * q];
        if (tid < 64) bs[tid] = b1[tid];
    }
    __syncthreads();

    float acc[8][8];
#pragma unroll
    for (int i = 0; i < 8; i++)
#pragma unroll
        for (int j = 0; j < 8; j++) acc[i][j] = 0.f;

    for (int kt = 0; kt < 2; kt++) {
        const int k0 = kt * 32;
        __syncthreads();
#pragma unroll
        for (int half = 0; half < 2; half++) {
            int lm = tid + 128 * half;
            int m = m0 + lm;
            if (m < N) {
                float d = g_dis[m];
                const float4* src = (const float4*)(g_agg1 + (size_t)m * 64 + k0);
#pragma unroll
                for (int q = 0; q < 8; q++) {
                    float4 v = src[q];
                    aT[4 * q + 0][lm] = elu_f(d * v.x + bs[k0 + 4 * q + 0]);
                    aT[4 * q + 1][lm] = elu_f(d * v.y + bs[k0 + 4 * q + 1]);
                    aT[4 * q + 2][lm] = elu_f(d * v.z + bs[k0 + 4 * q + 2]);
                    aT[4 * q + 3][lm] = elu_f(d * v.w + bs[k0 + 4 * q + 3]);
                }
            } else {
#pragma unroll
                for (int q = 0; q < 32; q++) aT[q][lm] = 0.f;
            }
        }
        __syncthreads();

#pragma unroll
        for (int kk = 0; kk < 32; kk++) {
            float4 xa = *(const float4*)&aT[kk][r0];
            float4 xb = *(const float4*)&aT[kk][r0 + 4];
            float4 wa = *(const float4*)&Wt[k0 + kk][c0];
            float4 wb = *(const float4*)&Wt[k0 + kk][c0 + 4];
            float xs[8] = {xa.x, xa.y, xa.z, xa.w, xb.x, xb.y, xb.z, xb.w};
            float ws[8] = {wa.x, wa.y, wa.z, wa.w, wb.x, wb.y, wb.z, wb.w};
#pragma unroll
            for (int i = 0; i < 8; i++)
#pragma unroll
                for (int j = 0; j < 8; j++) acc[i][j] += xs[i] * ws[j];
        }
    }

#pragma unroll
    for (int i = 0; i < 8; i++) {
        int m = m0 + r0 + i;
        if (m >= N) break;
        float d = g_dis[m];
        float4 a = make_float4(acc[i][0] * d, acc[i][1] * d, acc[i][2] * d, acc[i][3] * d);
        float4 b = make_float4(acc[i][4] * d, acc[i][5] * d, acc[i][6] * d, acc[i][7] * d);
        float4* o1 = (float4*)(g_h2s + (size_t)m * 32 + c0);
        o1[0] = a; o1[1] = b;
    }
}

// ---------------- aggregation 2 + final head fused (pipelined unroll-8) ----------------
__global__ void k_agg2_final(const float* __restrict__ Wc, const float* __restrict__ b2,
                             const float* __restrict__ bc, float* __restrict__ out, int N) {
    __shared__ float wcs[32], b2s[32];
    if (threadIdx.x < 32) {
        wcs[threadIdx.x] = Wc[threadIdx.x];
        b2s[threadIdx.x] = b2[threadIdx.x];
    }
    __syncthreads();
    int t = blockIdx.x * blockDim.x + threadIdx.x;
    int node = t >> 3, l = t & 7;
    bool valid = (node < N);
    int nd = valid ? node : N - 1;   // keep all lanes resident for shfl

    int s = g_ptr[nd], e = g_ptr[nd + 1];
    const float4* H = (const float4*)g_h2s;
    float4 accA = H[(size_t)nd * 8 + l];   // self loop
    float4 accB = make_float4(0.f, 0.f, 0.f, 0.f);
    int i = s;
    for (; i + 8 <= e; i += 8) {
        int r[8];
#pragma unroll
        for (int q = 0; q < 8; q++) r[q] = g_src[i + q];
        float4 v[8];
#pragma unroll
        for (int q = 0; q < 8; q++) v[q] = H[(size_t)r[q] * 8 + l];
#pragma unroll
        for (int q = 0; q < 4; q++) {
            accA.x += v[q].x; accA.y += v[q].y; accA.z += v[q].z; accA.w += v[q].w;
        }
#pragma unroll
        for (int q = 4; q < 8; q++) {
            accB.x += v[q].x; accB.y += v[q].y; accB.z += v[q].z; accB.w += v[q].w;
        }
    }
    for (; i < e; i++) {
        int r = g_src[i];
        float4 a = H[(size_t)r * 8 + l];
        accA.x += a.x; accA.y += a.y; accA.z += a.z; accA.w += a.w;
    }
    accA.x += accB.x; accA.y += accB.y; accA.z += accB.z; accA.w += accB.w;

    float d = g_dis[nd];
    int j0 = l * 4;
    float part = elu_f(d * accA.x + b2s[j0 + 0]) * wcs[j0 + 0]
               + elu_f(d * accA.y + b2s[j0 + 1]) * wcs[j0 + 1]
               + elu_f(d * accA.z + b2s[j0 + 2]) * wcs[j0 + 2]
               + elu_f(d * accA.w + b2s[j0 + 3]) * wcs[j0 + 3];
    part += __shfl_xor_sync(0xFFFFFFFFu, part, 4);
    part += __shfl_xor_sync(0xFFFFFFFFu, part, 2);
    part += __shfl_xor_sync(0xFFFFFFFFu, part, 1);
    if (valid && l == 0) out[node] = part + __ldg(bc);
}

extern "C" void kernel_launch(void* const* d_in, const int* in_sizes, int n_in,
                              void* d_out, int out_size) {
    const float* x = (const float*)d_in[0];
    const int* ei = (const int*)d_in[1];   // int32
    const float* W1 = (const float*)d_in[2];
    const float* b1 = (const float*)d_in[3];
    const float* W2 = (const float*)d_in[4];
    const float* b2 = (const float*)d_in[5];
    const float* Wc = (const float*)d_in[6];
    const float* bc = (const float*)d_in[7];
    float* out = (float*)d_out;

    int N = in_sizes[0] / 256;
    int E = in_sizes[1] / 2;
    const int* erow = ei;       // source (gather)
    const int* ecol = ei + E;   // target (aggregation)

    const int T = 256;
    // CSR build (shared by both layers) + dis
    k_zero_cnt<<<(N + T - 1) / T, T>>>(N);
    {
        int th = (E + 3) / 4;
        k_count<<<(th + T - 1) / T, T>>>(ecol, E);
    }
    k_scan<<<1, 1024>>>(N);
    {
        int th = (E + 3) / 4;
        k_fill<<<(th + T - 1) / T, T>>>(erow, ecol, E);
    }
    // layer 1
    k_gemm1<<<(N + 255) / 256, 256>>>(x, W1, N);
    {
        long long th = (long long)N * 16;
        k_agg1<<<(int)((th + T - 1) / T), T>>>(N);
    }
    // layer 2
    k_gemm2<<<(N + 255) / 256, 128>>>(W2, b1, N);
    // aggregation 2 + head fused
    {
        long long th = (long long)N * 8;
        k_agg2_final<<<(int)((th + T - 1) / T), T>>>(Wc, b2, bc, out, N);
    }
}

// round 17
// speedup vs baseline: 1.3012x; 1.2474x over previous
#include <cuda_runtime.h>
#include <math.h>

#define MAXN 100000
#define MAXE 3200000

__device__ int   g_cnt[MAXN];
__device__ float g_dis[MAXN];
__device__ float g_h1s[(size_t)MAXN * 64];   // h1 * dis[row]
__device__ float g_agg1[(size_t)MAXN * 64];  // Σ_in h1s + self (unscaled by dis[col])
__device__ float g_h2s[(size_t)MAXN * 32];   // h2 * dis[row]
__device__ float g_agg2[(size_t)MAXN * 32];

__device__ __forceinline__ float elu_f(float v) { return v > 0.f ? v : expm1f(v); }

// ---------------- degree / normalization ----------------
__global__ void k_zero_cnt(int N) {
    int i = blockIdx.x * blockDim.x + threadIdx.x;
    if (i < N) g_cnt[i] = 0;
}

// 4 edges/thread, int REDs (no return) pipeline freely
__global__ void k_count(const int* __restrict__ col, int E) {
    int base = (blockIdx.x * blockDim.x + threadIdx.x) * 4;
    if (base >= E) return;
    int n = min(4, E - base);
    int c[4];
#pragma unroll
    for (int q = 0; q < 4; q++) if (q < n) c[q] = col[base + q];
#pragma unroll
    for (int q = 0; q < 4; q++) if (q < n) atomicAdd(&g_cnt[c[q]], 1);
}

__global__ void k_dis(int N) {
    int i = blockIdx.x * blockDim.x + threadIdx.x;
    if (i < N) g_dis[i] = rsqrtf((float)g_cnt[i] + 1.0f);   // +1 = self loop
}

// ---------------- GEMM 1: h1s = (x @ W1) * dis[row]  (256 -> 64) ----------------
// Register-tiled 256x64 block, 8x8 micro-tile. Epilogue dual-writes h1s + agg1 (self-loop init).
__global__ void __launch_bounds__(256) k_gemm1(const float* __restrict__ x,
                                               const float* __restrict__ W1, int N) {
    __shared__ float xT[32][260];
    __shared__ float Wt[32][64];

    const int tid = threadIdx.x;
    const int m0 = blockIdx.x * 256;
    const int r0 = (tid >> 3) * 8;
    const int c0 = (tid & 7) * 8;

    float acc[8][8];
#pragma unroll
    for (int i = 0; i < 8; i++)
#pragma unroll
        for (int j = 0; j < 8; j++) acc[i][j] = 0.f;

    const int myrow = m0 + tid;
    for (int kt = 0; kt < 8; kt++) {
        const int k0 = kt * 32;
        {
            float4 v[8];
            if (myrow < N) {
                const float4* src = (const float4*)(x + (size_t)myrow * 256 + k0);
#pragma unroll
                for (int q = 0; q < 8; q++) v[q] = src[q];
            } else {
#pragma unroll
                for (int q = 0; q < 8; q++) v[q] = make_float4(0.f, 0.f, 0.f, 0.f);
            }
#pragma unroll
            for (int q = 0; q < 8; q++) {
                xT[4 * q + 0][tid] = v[q].x;
                xT[4 * q + 1][tid] = v[q].y;
                xT[4 * q + 2][tid] = v[q].z;
                xT[4 * q + 3][tid] = v[q].w;
            }
        }
        {
            const float4* src = (const float4*)(W1 + (size_t)k0 * 64);
            float4* dst = (float4*)Wt;
            dst[tid] = src[tid];
            dst[tid + 256] = src[tid + 256];
        }
        __syncthreads();

#pragma unroll
        for (int kk = 0; kk < 32; kk++) {
            float4 xa = *(const float4*)&xT[kk][r0];
            float4 xb = *(const float4*)&xT[kk][r0 + 4];
            float4 wa = *(const float4*)&Wt[kk][c0];
            float4 wb = *(const float4*)&Wt[kk][c0 + 4];
            float xs[8] = {xa.x, xa.y, xa.z, xa.w, xb.x, xb.y, xb.z, xb.w};
            float ws[8] = {wa.x, wa.y, wa.z, wa.w, wb.x, wb.y, wb.z, wb.w};
#pragma unroll
            for (int i = 0; i < 8; i++)
#pragma unroll
                for (int j = 0; j < 8; j++) acc[i][j] += xs[i] * ws[j];
        }
        __syncthreads();
    }

#pragma unroll
    for (int i = 0; i < 8; i++) {
        int m = m0 + r0 + i;
        if (m >= N) break;
        float d = g_dis[m];
        float4 a = make_float4(acc[i][0] * d, acc[i][1] * d, acc[i][2] * d, acc[i][3] * d);
        float4 b = make_float4(acc[i][4] * d, acc[i][5] * d, acc[i][6] * d, acc[i][7] * d);
        float4* o1 = (float4*)(g_h1s + (size_t)m * 64 + c0);
        float4* o2 = (float4*)(g_agg1 + (size_t)m * 64 + c0);
        o1[0] = a; o1[1] = b;
        o2[0] = a; o2[1] = b;
    }
}

// ---------------- edge scatter (batched 4 edges/thread): agg[c] += h_s[r] ----------------
// lane l handles 16B slice l of 4 consecutive edges: 4 gathers in flight, then 4 REDs.
__global__ void k_scatter1(const int* __restrict__ rowi, const int* __restrict__ coli, int E) {
    long long t = (long long)blockIdx.x * blockDim.x + threadIdx.x;
    int p = (int)(t >> 4);
    int l = (int)(t & 15);
    int e0 = p * 4;
    if (e0 >= E) return;
    int n = min(4, E - e0);
    int r[4], c[4];
#pragma unroll
    for (int q = 0; q < 4; q++) if (q < n) { r[q] = __ldg(rowi + e0 + q); c[q] = __ldg(coli + e0 + q); }
    const float4* H = (const float4*)g_h1s;
    float4 v[4];
#pragma unroll
    for (int q = 0; q < 4; q++) if (q < n) v[q] = H[(size_t)r[q] * 16 + l];
#pragma unroll
    for (int q = 0; q < 4; q++) if (q < n) {
        float* dst = g_agg1 + (size_t)c[q] * 64 + l * 4;
        asm volatile("red.global.add.v4.f32 [%0], {%1,%2,%3,%4};" ::
                     "l"(dst), "f"(v[q].x), "f"(v[q].y), "f"(v[q].z), "f"(v[q].w)
                     : "memory");
    }
}

__global__ void k_scatter2(const int* __restrict__ rowi, const int* __restrict__ coli, int E) {
    long long t = (long long)blockIdx.x * blockDim.x + threadIdx.x;
    int p = (int)(t >> 3);
    int l = (int)(t & 7);
    int e0 = p * 4;
    if (e0 >= E) return;
    int n = min(4, E - e0);
    int r[4], c[4];
#pragma unroll
    for (int q = 0; q < 4; q++) if (q < n) { r[q] = __ldg(rowi + e0 + q); c[q] = __ldg(coli + e0 + q); }
    const float4* H = (const float4*)g_h2s;
    float4 v[4];
#pragma unroll
    for (int q = 0; q < 4; q++) if (q < n) v[q] = H[(size_t)r[q] * 8 + l];
#pragma unroll
    for (int q = 0; q < 4; q++) if (q < n) {
        float* dst = g_agg2 + (size_t)c[q] * 32 + l * 4;
        asm volatile("red.global.add.v4.f32 [%0], {%1,%2,%3,%4};" ::
                     "l"(dst), "f"(v[q].x), "f"(v[q].y), "f"(v[q].z), "f"(v[q].w)
                     : "memory");
    }
}

// ---------------- GEMM 2: h2s = (elu(dis*agg1 + b1) @ W2) * dis  (64 -> 32) ----------------
__global__ void __launch_bounds__(128) k_gemm2(const float* __restrict__ W2,
                                               const float* __restrict__ b1, int N) {
    __shared__ float aT[32][260];
    __shared__ float Wt[64][32];
    __shared__ float bs[64];

    const int tid = threadIdx.x;
    const int m0 = blockIdx.x * 256;
    const int r0 = (tid >> 2) * 8;
    const int c0 = (tid & 3) * 8;

    {
        const float4* src = (const float4*)W2;
        float4* dst = (float4*)Wt;
#pragma unroll
        for (int q = 0; q < 4; q++) dst[tid + 128 * q] = src[tid + 128 * q];
        if (tid < 64) bs[tid] = b1[tid];
    }
    __syncthreads();

    float acc[8][8];
#pragma unroll
    for (int i = 0; i < 8; i++)
#pragma unroll
        for (int j = 0; j < 8; j++) acc[i][j] = 0.f;

    for (int kt = 0; kt < 2; kt++) {
        const int k0 = kt * 32;
        __syncthreads();
#pragma unroll
        for (int half = 0; half < 2; half++) {
            int lm = tid + 128 * half;
            int m = m0 + lm;
            if (m < N) {
                float d = g_dis[m];
                const float4* src = (const float4*)(g_agg1 + (size_t)m * 64 + k0);
#pragma unroll
                for (int q = 0; q < 8; q++) {
                    float4 v = src[q];
                    aT[4 * q + 0][lm] = elu_f(d * v.x + bs[k0 + 4 * q + 0]);
                    aT[4 * q + 1][lm] = elu_f(d * v.y + bs[k0 + 4 * q + 1]);
                    aT[4 * q + 2][lm] = elu_f(d * v.z + bs[k0 + 4 * q + 2]);
                    aT[4 * q + 3][lm] = elu_f(d * v.w + bs[k0 + 4 * q + 3]);
                }
            } else {
#pragma unroll
                for (int q = 0; q < 32; q++) aT[q][lm] = 0.f;
            }
        }
        __syncthreads();

#pragma unroll
        for (int kk = 0; kk < 32; kk++) {
            float4 xa = *(const float4*)&aT[kk][r0];
            float4 xb = *(const float4*)&aT[kk][r0 + 4];
            float4 wa = *(const float4*)&Wt[k0 + kk][c0];
            float4 wb = *(const float4*)&Wt[k0 + kk][c0 + 4];
            float xs[8] = {xa.x, xa.y, xa.z, xa.w, xb.x, xb.y, xb.z, xb.w};
            float ws[8] = {wa.x, wa.y, wa.z, wa.w, wb.x, wb.y, wb.z, wb.w};
#pragma unroll
            for (int i = 0; i < 8; i++)
#pragma unroll
                for (int j = 0; j < 8; j++) acc[i][j] += xs[i] * ws[j];
        }
    }

#pragma unroll
    for (int i = 0; i < 8; i++) {
        int m = m0 + r0 + i;
        if (m >= N) break;
        float d = g_dis[m];
        float4 a = make_float4(acc[i][0] * d, acc[i][1] * d, acc[i][2] * d, acc[i][3] * d);
        float4 b = make_float4(acc[i][4] * d, acc[i][5] * d, acc[i][6] * d, acc[i][7] * d);
        float4* o1 = (float4*)(g_h2s + (size_t)m * 32 + c0);
        float4* o2 = (float4*)(g_agg2 + (size_t)m * 32 + c0);
        o1[0] = a; o1[1] = b;
        o2[0] = a; o2[1] = b;
    }
}

// ---------------- final head: out = elu(dis*agg2 + b2) . Wc + bc ----------------
__global__ void k_final(const float* __restrict__ Wc, const float* __restrict__ b2,
                        const float* __restrict__ bc, float* __restrict__ out, int N) {
    __shared__ float wcs[32], b2s[32];
    if (threadIdx.x < 32) {
        wcs[threadIdx.x] = Wc[threadIdx.x];
        b2s[threadIdx.x] = b2[threadIdx.x];
    }
    __syncthreads();
    int i = blockIdx.x * blockDim.x + threadIdx.x;
    if (i >= N) return;
    float d = g_dis[i];
    const float4* A4 = (const float4*)(g_agg2 + (size_t)i * 32);
    float s = 0.f;
#pragma unroll
    for (int j4 = 0; j4 < 8; j4++) {
        float4 v = A4[j4];
        s += elu_f(d * v.x + b2s[4 * j4 + 0]) * wcs[4 * j4 + 0];
        s += elu_f(d * v.y + b2s[4 * j4 + 1]) * wcs[4 * j4 + 1];
        s += elu_f(d * v.z + b2s[4 * j4 + 2]) * wcs[4 * j4 + 2];
        s += elu_f(d * v.w + b2s[4 * j4 + 3]) * wcs[4 * j4 + 3];
    }
    out[i] = s + __ldg(bc);
}

extern "C" void kernel_launch(void* const* d_in, const int* in_sizes, int n_in,
                              void* d_out, int out_size) {
    const float* x = (const float*)d_in[0];
    const int* ei = (const int*)d_in[1];   // int32
    const float* W1 = (const float*)d_in[2];
    const float* b1 = (const float*)d_in[3];
    const float* W2 = (const float*)d_in[4];
    const float* b2 = (const float*)d_in[5];
    const float* Wc = (const float*)d_in[6];
    const float* bc = (const float*)d_in[7];
    float* out = (float*)d_out;

    int N = in_sizes[0] / 256;
    int E = in_sizes[1] / 2;
    const int* erow = ei;       // source (gather)
    const int* ecol = ei + E;   // target (aggregation)

    const int T = 256;
    // normalization
    k_zero_cnt<<<(N + T - 1) / T, T>>>(N);
    {
        int th = (E + 3) / 4;
        k_count<<<(th + T - 1) / T, T>>>(ecol, E);
    }
    k_dis<<<(N + T - 1) / T, T>>>(N);
    // layer 1
    k_gemm1<<<(N + 255) / 256, 256>>>(x, W1, N);
    {
        long long th = ((long long)(E + 3) / 4) * 16;
        k_scatter1<<<(int)((th + T - 1) / T), T>>>(erow, ecol, E);
    }
    // layer 2
    k_gemm2<<<(N + 255) / 256, 128>>>(W2, b1, N);
    {
        long long th = ((long long)(E + 3) / 4) * 8;
        k_scatter2<<<(int)((th + T - 1) / T), T>>>(erow, ecol, E);
    }
    // head
    k_final<<<(N + T - 1) / T, T>>>(Wc, b2, bc, out, N);
}